// round 3
// baseline (speedup 1.0000x reference)
#include <cuda_runtime.h>
#include <math.h>

#define BB 32
#define SS 256
#define EE 300
#define EP 304
#define HH 256
#define T4H 1024
#define NT 19
#define TSTART 17
#define TSTOP 18

typedef unsigned long long ull;

__device__ __forceinline__ ull fma2(ull a, ull b, ull c) {
    ull d;
    asm("fma.rn.f32x2 %0, %1, %2, %3;" : "=l"(d) : "l"(a), "l"(b), "l"(c));
    return d;
}
__device__ __forceinline__ ull pack2(float lo, float hi) {
    ull r;
    asm("mov.b64 %0, {%1, %2};" : "=l"(r) : "f"(lo), "f"(hi));
    return r;
}

// ---------------- device scratch (no cudaMalloc allowed) ----------------
__device__ float    g_X[(size_t)BB * SS * EP];            // [n][e], n = t*32 + b
__device__ float    g_xg[(size_t)2 * SS * T4H * BB];      // [d][t][row][b]
__device__ float    g_h[(size_t)2 * SS * HH * BB];        // [d][t][k][b]
__device__ float    g_logits[(size_t)BB * SS * NT];       // [b][t][tag]
__device__ int      g_ptr[(size_t)BB * SS * NT];          // viterbi backpointers
__device__ float    g_nll[BB];
__device__ unsigned g_bar[SS];                            // per-step barrier counters

// ---------------- zero output + barrier counters ----------------
__global__ void zero_out_kernel(float* out, int n) {
    int i = blockIdx.x * blockDim.x + threadIdx.x;
    if (i < n) out[i] = 0.0f;
    if (i < SS) g_bar[i] = 0u;
}

// ---------------- embedding gather + mask -> padded X [8192][304] ----------------
__global__ void embed_kernel(const int* __restrict__ word, const int* __restrict__ mask,
                             const float* __restrict__ emb) {
    int idx = blockIdx.x * blockDim.x + threadIdx.x;
    int total = BB * SS * (EP / 4);
    if (idx >= total) return;
    int n = idx / (EP / 4), q = idx - n * (EP / 4);
    int t = n >> 5, b = n & 31;
    int w = word[b * SS + t];
    float m = (float)mask[b * SS + t];
    int e = q * 4;
    float4 v;
    if (e < EE) {
        float4 ev = *(const float4*)(emb + (size_t)w * EE + e);
        v.x = ev.x * m; v.y = ev.y * m; v.z = ev.z * m; v.w = ev.w * m;
    } else {
        v.x = v.y = v.z = v.w = 0.0f;
    }
    ((float4*)g_X)[(size_t)n * (EP / 4) + q] = v;
}

// ---------------- input-transform GEMM (f32x2): xg = X @ Wih_d.T + bih + bhh ----------------
__global__ __launch_bounds__(256) void gemm_xg_kernel(
    const float* __restrict__ WihF, const float* __restrict__ WihB,
    const float* __restrict__ bihF, const float* __restrict__ bhhF,
    const float* __restrict__ bihB, const float* __restrict__ bhhB) {
    __shared__ ull   As[16][64];   // duplicated {w,w} pairs: [k][row]
    __shared__ float Xs[16][68];   // [k][col], pitch 68 keeps 16B alignment (68*4=272=17*16)
    int d = blockIdx.z;
    const float* Wih = d ? WihB : WihF;
    const float* bih = d ? bihB : bihF;
    const float* bhh = d ? bhhB : bhhF;
    int m0 = blockIdx.y * 64, n0 = blockIdx.x * 64;
    int tid = threadIdx.x;
    int lm = tid >> 2, kq = (tid & 3) * 4;
    int tx = tid & 15, ty = tid >> 4;
    ull acc[4][2];
#pragma unroll
    for (int i = 0; i < 4; i++) { acc[i][0] = 0ULL; acc[i][1] = 0ULL; }

    for (int e0 = 0; e0 < EP; e0 += 16) {
        float4 a;
        if (e0 + kq < EE) {
            a = *(const float4*)(Wih + (size_t)(m0 + lm) * EE + e0 + kq);
        } else {
            a.x = a.y = a.z = a.w = 0.0f;
        }
        As[kq + 0][lm] = pack2(a.x, a.x);
        As[kq + 1][lm] = pack2(a.y, a.y);
        As[kq + 2][lm] = pack2(a.z, a.z);
        As[kq + 3][lm] = pack2(a.w, a.w);
        float4 xv = *(const float4*)(g_X + (size_t)(n0 + lm) * EP + e0 + kq);
        Xs[kq + 0][lm] = xv.x; Xs[kq + 1][lm] = xv.y; Xs[kq + 2][lm] = xv.z; Xs[kq + 3][lm] = xv.w;
        __syncthreads();
#pragma unroll
        for (int k = 0; k < 16; k++) {
            ulonglong2 w01 = *(const ulonglong2*)&As[k][ty * 4];
            ulonglong2 w23 = *(const ulonglong2*)&As[k][ty * 4 + 2];
            ulonglong2 xx  = *(const ulonglong2*)&Xs[k][tx * 4];
            acc[0][0] = fma2(w01.x, xx.x, acc[0][0]); acc[0][1] = fma2(w01.x, xx.y, acc[0][1]);
            acc[1][0] = fma2(w01.y, xx.x, acc[1][0]); acc[1][1] = fma2(w01.y, xx.y, acc[1][1]);
            acc[2][0] = fma2(w23.x, xx.x, acc[2][0]); acc[2][1] = fma2(w23.x, xx.y, acc[2][1]);
            acc[3][0] = fma2(w23.y, xx.x, acc[3][0]); acc[3][1] = fma2(w23.y, xx.y, acc[3][1]);
        }
        __syncthreads();
    }
#pragma unroll
    for (int i = 0; i < 4; i++) {
        int row = m0 + ty * 4 + i;
        float bias = bih[row] + bhh[row];
        float2 f0 = *(float2*)&acc[i][0];
        float2 f1 = *(float2*)&acc[i][1];
        float vals[4] = {f0.x, f0.y, f1.x, f1.y};
#pragma unroll
        for (int j = 0; j < 4; j++) {
            int n = n0 + tx * 4 + j;
            int tt = n >> 5, bb2 = n & 31;
            g_xg[(((size_t)d * SS + tt) * T4H + row) * BB + bb2] = vals[j] + bias;
        }
    }
}

// ---------------- persistent BiLSTM recurrence (f32x2, direct global h reads) ----------------
// 128 blocks: bid>>6 = dir, bid&63 = slice m (4 hidden units -> 16 gate rows).
__global__ __launch_bounds__(128, 1) void lstm_kernel(
    const float* __restrict__ WhhF, const float* __restrict__ WhhB) {
    extern __shared__ ull sm8[];
    ull*   W_dup = sm8;                  // [256 k][16 r] {w,w} pairs  (4096 ull = 32KB)
    ull*   part  = sm8 + 4096;           // [4 w][16 r][17 pairs]      (1088 ull)
    float* c_s   = (float*)(sm8 + 4096 + 1088);  // [128]

    int tid = threadIdx.x, bid = blockIdx.x;
    int d = bid >> 6, m = bid & 63;
    const float* Whh = d ? WhhB : WhhF;

    // stage duplicated Whh slice: W_dup[k*16 + r], r = gg*4+u -> gate row gg*256 + m*4 + u
    for (int i = tid; i < 4096; i += 128) {
        int r = i & 15, k = i >> 4;
        int gg = r >> 2, uu = r & 3;
        float w = Whh[(size_t)(gg * HH + m * 4 + uu) * HH + k];
        W_dup[k * 16 + r] = pack2(w, w);
    }
    c_s[tid] = 0.0f;
    __syncthreads();

    int lane = tid & 31, w = tid >> 5;
    int ggl = lane & 3, bg = lane >> 2;
    const ulonglong2* Wd2 = (const ulonglong2*)W_dup;
    int u = tid >> 5, b = tid & 31;   // cell-update mapping

    for (int it = 0; it < SS; it++) {
        int t = d ? (SS - 1 - it) : it;

        // prefetch this step's xg into registers (hides DRAM latency behind GEMV)
        float xgv[4];
        const float* xgb = g_xg + ((size_t)(d * SS + t) * T4H) * BB;
#pragma unroll
        for (int gg = 0; gg < 4; gg++)
            xgv[gg] = xgb[(size_t)(gg * HH + m * 4 + u) * BB + b];

        if (it > 0) {
            int tp = d ? t + 1 : t - 1;
            const float* hbase = g_h + ((size_t)(d * SS + tp) * HH) * BB + bg * 4;
            ull a[4][2];
#pragma unroll
            for (int i = 0; i < 4; i++) { a[i][0] = 0ULL; a[i][1] = 0ULL; }
            int k0 = w * 64;
#pragma unroll 8
            for (int k = k0; k < k0 + 64; k++) {
                ulonglong2 w01 = Wd2[k * 8 + ggl * 2];
                ulonglong2 w23 = Wd2[k * 8 + ggl * 2 + 1];
                ulonglong2 hh  = *(const ulonglong2*)(hbase + (size_t)k * BB);
                a[0][0] = fma2(w01.x, hh.x, a[0][0]); a[0][1] = fma2(w01.x, hh.y, a[0][1]);
                a[1][0] = fma2(w01.y, hh.x, a[1][0]); a[1][1] = fma2(w01.y, hh.y, a[1][1]);
                a[2][0] = fma2(w23.x, hh.x, a[2][0]); a[2][1] = fma2(w23.x, hh.y, a[2][1]);
                a[3][0] = fma2(w23.y, hh.x, a[3][0]); a[3][1] = fma2(w23.y, hh.y, a[3][1]);
            }
#pragma unroll
            for (int i = 0; i < 4; i++) {
                ull* pr = part + (size_t)(w * 16 + ggl * 4 + i) * 17 + bg * 2;
                pr[0] = a[i][0]; pr[1] = a[i][1];
            }
        }
        __syncthreads();

        // cell update: thread -> (u, b)
        {
            const float* pf = (const float*)part;
            float g[4];
#pragma unroll
            for (int gg = 0; gg < 4; gg++) {
                float s = xgv[gg];
                if (it > 0) {
                    int r = gg * 4 + u;
#pragma unroll
                    for (int wi = 0; wi < 4; wi++)
                        s += pf[(((size_t)wi * 16 + r) * 17 + (b >> 1)) * 2 + (b & 1)];
                }
                g[gg] = s;
            }
            float iv = 1.0f / (1.0f + expf(-g[0]));
            float fv = 1.0f / (1.0f + expf(-g[1]));
            float gv = tanhf(g[2]);
            float ov = 1.0f / (1.0f + expf(-g[3]));
            float c = fv * c_s[tid] + iv * gv;
            c_s[tid] = c;
            g_h[((size_t)(d * SS + t) * HH + m * 4 + u) * BB + b] = ov * tanhf(c);
        }
        __threadfence();
        __syncthreads();
        if (tid == 0) {
            atomicAdd(&g_bar[it], 1u);
            volatile unsigned* p = &g_bar[it];
            while (*p < 128u) { }
        }
        __syncthreads();
    }
}

// ---------------- logits: [b][t][tag] = hcat . W_tag[tag] + b_tag ----------------
__global__ __launch_bounds__(256) void logits_kernel(const float* __restrict__ Wtag,
                                                     const float* __restrict__ btag) {
    extern __shared__ float hb[];  // [512 k][32 b]
    int t = blockIdx.x;
    int tid = threadIdx.x;
    for (int dd = 0; dd < 2; dd++) {
        const float4* src = (const float4*)(g_h + (size_t)(dd * SS + t) * HH * BB);
        float4* dst = (float4*)(hb + (size_t)dd * HH * BB);
        for (int i = tid; i < 2048; i += 256) dst[i] = src[i];
    }
    __syncthreads();
    for (int o = tid; o < BB * NT; o += 256) {
        int tag = o >> 5;
        int b = o & 31;
        float acc = btag[tag];
        const float* wr = Wtag + (size_t)tag * (2 * HH);
#pragma unroll 8
        for (int k = 0; k < 2 * HH; k++) acc += hb[k * BB + b] * wr[k];
        g_logits[((size_t)b * SS + t) * NT + tag] = acc;
    }
}

// ---------------- merged CRF forward + Viterbi (grid 32 x 2) ----------------
__global__ void crf_vit_kernel(const int* __restrict__ mask, const int* __restrict__ labels,
                               const float* __restrict__ trans, float* __restrict__ out) {
    __shared__ float tr[NT * NT];
    __shared__ float st[NT];
    int b = blockIdx.x, j = threadIdx.x;
    for (int i = j; i < NT * NT; i += 32) tr[i] = trans[i];
    __syncthreads();

    if (blockIdx.y == 0) {
        // ---- CRF NLL ----
        if (j < NT) st[j] = g_logits[((size_t)b * SS) * NT + j] + tr[TSTART * NT + j];
        __syncthreads();
        for (int t = 1; t < SS; t++) {
            int mt = mask[b * SS + t];
            float nv = 0.0f;
            if (j < NT) {
                float mx = -1e30f;
#pragma unroll
                for (int i = 0; i < NT; i++) mx = fmaxf(mx, st[i] + tr[i * NT + j]);
                float sum = 0.0f;
#pragma unroll
                for (int i = 0; i < NT; i++) sum += expf(st[i] + tr[i * NT + j] - mx);
                nv = mx + logf(sum) + g_logits[((size_t)b * SS + t) * NT + j];
            }
            __syncthreads();
            if (j < NT && mt > 0) st[j] = nv;
            __syncthreads();
        }
        if (j == 0) {
            float mx = -1e30f;
            for (int i = 0; i < NT; i++) mx = fmaxf(mx, st[i] + tr[i * NT + TSTOP]);
            float sum = 0.0f;
            for (int i = 0; i < NT; i++) sum += expf(st[i] + tr[i * NT + TSTOP] - mx);
            float logZ = mx + logf(sum);
            float gold = 0.0f;
            int prev = TSTART, len = 0;
            for (int t = 0; t < SS; t++) {
                int lab = labels[b * SS + t];
                if (mask[b * SS + t] > 0) {
                    gold += tr[prev * NT + lab] + g_logits[((size_t)b * SS + t) * NT + lab];
                    len++;
                }
                prev = lab;
            }
            int last = labels[b * SS + len - 1];
            gold += tr[last * NT + TSTOP];
            g_nll[b] = logZ - gold;
        }
    } else {
        // ---- Viterbi ----
        if (j < NT) st[j] = g_logits[((size_t)b * SS) * NT + j] + tr[TSTART * NT + j];
        __syncthreads();
        for (int t = 1; t < SS; t++) {
            int mt = mask[b * SS + t];
            float nv = 0.0f;
            int arg = j;
            if (j < NT) {
                float best = -1e30f;
                int bi = 0;
#pragma unroll
                for (int i = 0; i < NT; i++) {
                    float v = st[i] + tr[i * NT + j];
                    if (v > best) { best = v; bi = i; }  // strict '>' => first max (jnp.argmax)
                }
                nv = best + g_logits[((size_t)b * SS + t) * NT + j];
                if (mt > 0) arg = bi;
            }
            __syncthreads();
            if (j < NT) {
                if (mt > 0) st[j] = nv;
                g_ptr[((size_t)b * SS + t) * NT + j] = arg;
            }
            __syncthreads();
        }
        if (j == 0) {
            float best = -1e30f;
            int bl = 0;
            for (int i = 0; i < NT; i++) {
                float v = st[i] + tr[i * NT + TSTOP];
                if (v > best) { best = v; bl = i; }
            }
            int tag = bl;
            for (int t = SS - 1; t >= 1; t--) {
                out[1 + b * SS + t] = (float)(mask[b * SS + t] > 0 ? tag : 0);
                tag = g_ptr[((size_t)b * SS + t) * NT + tag];
            }
            out[1 + b * SS + 0] = (float)(mask[b * SS + 0] > 0 ? tag : 0);
        }
    }
}

__global__ void finalize_kernel(float* out) {
    if (threadIdx.x == 0) {
        float s = 0.0f;
        for (int i = 0; i < BB; i++) s += g_nll[i];
        out[0] = s / (float)BB;
    }
}

extern "C" void kernel_launch(void* const* d_in, const int* in_sizes, int n_in,
                              void* d_out, int out_size) {
    // metadata order: word, mask, labels, labels_token, [data_type], emb, WihF, WhhF,
    // bihF, bhhF, WihB, WhhB, bihB, bhhB, Wtag, btag, trans
    int o = (in_sizes[4] == 1) ? 0 : -1;  // data_type scalar present or dropped
    const int*   word   = (const int*)d_in[0];
    const int*   mask   = (const int*)d_in[1];
    const int*   labels = (const int*)d_in[2];
    const float* emb    = (const float*)d_in[5 + o];
    const float* WihF   = (const float*)d_in[6 + o];
    const float* WhhF   = (const float*)d_in[7 + o];
    const float* bihF   = (const float*)d_in[8 + o];
    const float* bhhF   = (const float*)d_in[9 + o];
    const float* WihB   = (const float*)d_in[10 + o];
    const float* WhhB   = (const float*)d_in[11 + o];
    const float* bihB   = (const float*)d_in[12 + o];
    const float* bhhB   = (const float*)d_in[13 + o];
    const float* Wtag   = (const float*)d_in[14 + o];
    const float* btag   = (const float*)d_in[15 + o];
    const float* trans  = (const float*)d_in[16 + o];
    float* out = (float*)d_out;

    const int lstm_smem = (4096 + 1088) * 8 + 128 * 4;  // 41984 B
    cudaFuncSetAttribute(lstm_kernel, cudaFuncAttributeMaxDynamicSharedMemorySize, lstm_smem);
    cudaFuncSetAttribute(logits_kernel, cudaFuncAttributeMaxDynamicSharedMemorySize, 65536);

    int nz = out_size > SS ? out_size : SS;
    zero_out_kernel<<<(nz + 255) / 256, 256>>>(out, out_size);
    embed_kernel<<<(BB * SS * (EP / 4) + 255) / 256, 256>>>(word, mask, emb);
    {
        dim3 grid(BB * SS / 64, T4H / 64, 2);
        gemm_xg_kernel<<<grid, 256>>>(WihF, WihB, bihF, bhhF, bihB, bhhB);
    }
    lstm_kernel<<<128, 128, lstm_smem>>>(WhhF, WhhB);
    logits_kernel<<<SS, 256, 65536>>>(Wtag, btag);
    crf_vit_kernel<<<dim3(BB, 2), 32>>>(mask, labels, trans, out);
    finalize_kernel<<<1, 32>>>(out);
}

// round 4
// speedup vs baseline: 1.1163x; 1.1163x over previous
#include <cuda_runtime.h>
#include <math.h>

#define BB 32
#define SS 256
#define EE 300
#define EP 304
#define HH 256
#define T4H 1024
#define NT 19
#define TSTART 17
#define TSTOP 18

typedef unsigned long long ull;

__device__ __forceinline__ ull fma2(ull a, ull b, ull c) {
    ull d;
    asm("fma.rn.f32x2 %0, %1, %2, %3;" : "=l"(d) : "l"(a), "l"(b), "l"(c));
    return d;
}
__device__ __forceinline__ ull pack2(float lo, float hi) {
    ull r;
    asm("mov.b64 %0, {%1, %2};" : "=l"(r) : "f"(lo), "f"(hi));
    return r;
}
__device__ __forceinline__ float fsigmoid(float x) {
    return 1.0f / (1.0f + __expf(-x));
}
__device__ __forceinline__ float ftanh_fast(float x) {
    // tanh(x) = 1 - 2/(exp(2x)+1); __expf rel err ~1e-7 -> safe for argmax margins
    return 1.0f - 2.0f / (__expf(2.0f * x) + 1.0f);
}

// ---------------- device scratch (no cudaMalloc allowed) ----------------
__device__ float    g_X[(size_t)BB * SS * EP];            // [n][e], n = t*32 + b
__device__ float    g_xg[(size_t)2 * SS * T4H * BB];      // [d][t][row][b]
__device__ float    g_h[(size_t)2 * SS * HH * BB];        // [d][t][k][b]
__device__ float    g_logits[(size_t)BB * SS * NT];       // [b][t][tag]
__device__ int      g_ptr[(size_t)BB * SS * NT];          // viterbi backpointers
__device__ float    g_nll[BB];
__device__ unsigned g_bar[2 * SS];                        // per-dir per-step barrier counters

// ---------------- zero output + barrier counters ----------------
__global__ void zero_out_kernel(float* out, int n) {
    int i = blockIdx.x * blockDim.x + threadIdx.x;
    if (i < n) out[i] = 0.0f;
    if (i < 2 * SS) g_bar[i] = 0u;
}

// ---------------- embedding gather + mask -> padded X [8192][304] ----------------
__global__ void embed_kernel(const int* __restrict__ word, const int* __restrict__ mask,
                             const float* __restrict__ emb) {
    int idx = blockIdx.x * blockDim.x + threadIdx.x;
    int total = BB * SS * (EP / 4);
    if (idx >= total) return;
    int n = idx / (EP / 4), q = idx - n * (EP / 4);
    int t = n >> 5, b = n & 31;
    int w = word[b * SS + t];
    float m = (float)mask[b * SS + t];
    int e = q * 4;
    float4 v;
    if (e < EE) {
        float4 ev = *(const float4*)(emb + (size_t)w * EE + e);
        v.x = ev.x * m; v.y = ev.y * m; v.z = ev.z * m; v.w = ev.w * m;
    } else {
        v.x = v.y = v.z = v.w = 0.0f;
    }
    ((float4*)g_X)[(size_t)n * (EP / 4) + q] = v;
}

// ---------------- input-transform GEMM (f32x2): xg = X @ Wih_d.T + bih + bhh ----------------
__global__ __launch_bounds__(256) void gemm_xg_kernel(
    const float* __restrict__ WihF, const float* __restrict__ WihB,
    const float* __restrict__ bihF, const float* __restrict__ bhhF,
    const float* __restrict__ bihB, const float* __restrict__ bhhB) {
    __shared__ ull   As[16][64];   // duplicated {w,w} pairs: [k][row]
    __shared__ float Xs[16][68];   // [k][col], pitch 68 keeps 16B alignment
    int d = blockIdx.z;
    const float* Wih = d ? WihB : WihF;
    const float* bih = d ? bihB : bihF;
    const float* bhh = d ? bhhB : bhhF;
    int m0 = blockIdx.y * 64, n0 = blockIdx.x * 64;
    int tid = threadIdx.x;
    int lm = tid >> 2, kq = (tid & 3) * 4;
    int tx = tid & 15, ty = tid >> 4;
    ull acc[4][2];
#pragma unroll
    for (int i = 0; i < 4; i++) { acc[i][0] = 0ULL; acc[i][1] = 0ULL; }

    for (int e0 = 0; e0 < EP; e0 += 16) {
        float4 a;
        if (e0 + kq < EE) {
            a = *(const float4*)(Wih + (size_t)(m0 + lm) * EE + e0 + kq);
        } else {
            a.x = a.y = a.z = a.w = 0.0f;
        }
        As[kq + 0][lm] = pack2(a.x, a.x);
        As[kq + 1][lm] = pack2(a.y, a.y);
        As[kq + 2][lm] = pack2(a.z, a.z);
        As[kq + 3][lm] = pack2(a.w, a.w);
        float4 xv = *(const float4*)(g_X + (size_t)(n0 + lm) * EP + e0 + kq);
        Xs[kq + 0][lm] = xv.x; Xs[kq + 1][lm] = xv.y; Xs[kq + 2][lm] = xv.z; Xs[kq + 3][lm] = xv.w;
        __syncthreads();
#pragma unroll
        for (int k = 0; k < 16; k++) {
            ulonglong2 w01 = *(const ulonglong2*)&As[k][ty * 4];
            ulonglong2 w23 = *(const ulonglong2*)&As[k][ty * 4 + 2];
            ulonglong2 xx  = *(const ulonglong2*)&Xs[k][tx * 4];
            acc[0][0] = fma2(w01.x, xx.x, acc[0][0]); acc[0][1] = fma2(w01.x, xx.y, acc[0][1]);
            acc[1][0] = fma2(w01.y, xx.x, acc[1][0]); acc[1][1] = fma2(w01.y, xx.y, acc[1][1]);
            acc[2][0] = fma2(w23.x, xx.x, acc[2][0]); acc[2][1] = fma2(w23.x, xx.y, acc[2][1]);
            acc[3][0] = fma2(w23.y, xx.x, acc[3][0]); acc[3][1] = fma2(w23.y, xx.y, acc[3][1]);
        }
        __syncthreads();
    }
#pragma unroll
    for (int i = 0; i < 4; i++) {
        int row = m0 + ty * 4 + i;
        float bias = bih[row] + bhh[row];
        float2 f0 = *(float2*)&acc[i][0];
        float2 f1 = *(float2*)&acc[i][1];
        float vals[4] = {f0.x, f0.y, f1.x, f1.y};
#pragma unroll
        for (int j = 0; j < 4; j++) {
            int n = n0 + tx * 4 + j;
            int tt = n >> 5, bb2 = n & 31;
            g_xg[(((size_t)d * SS + tt) * T4H + row) * BB + bb2] = vals[j] + bias;
        }
    }
}

// ---------------- persistent BiLSTM recurrence (f32x2 GEMV from smem h) ----------------
// 128 blocks: bid>>6 = dir, bid&63 = slice m (4 hidden units -> 16 gate rows).
__global__ __launch_bounds__(128, 1) void lstm_kernel(
    const float* __restrict__ WhhF, const float* __restrict__ WhhB) {
    extern __shared__ ull sm8[];
    ull*   W_dup = sm8;                     // [256 k][16 r] {w,w} pairs (4096 ull)
    float* h_s   = (float*)(sm8 + 4096);    // [256 k][32 b]            (8192 f = 4096 ull)
    ull*   part  = sm8 + 8192;              // [4 w][16 r][17 pairs]    (1088 ull)
    float* c_s   = (float*)(sm8 + 9280);    // [128]

    int tid = threadIdx.x, bid = blockIdx.x;
    int d = bid >> 6, m = bid & 63;
    const float* Whh = d ? WhhB : WhhF;

    // stage duplicated Whh slice: W_dup[k*16 + r], r = gg*4+u -> gate row gg*256 + m*4 + u
    for (int i = tid; i < 4096; i += 128) {
        int r = i & 15, k = i >> 4;
        int gg = r >> 2, uu = r & 3;
        float w = Whh[(size_t)(gg * HH + m * 4 + uu) * HH + k];
        W_dup[k * 16 + r] = pack2(w, w);
    }
    c_s[tid] = 0.0f;
    __syncthreads();

    int lane = tid & 31, w = tid >> 5;
    int ggl = lane & 3, bg = lane >> 2;
    const ulonglong2* Wd2 = (const ulonglong2*)W_dup;
    const ulonglong2* H2  = (const ulonglong2*)h_s;
    int u = tid >> 5, b = tid & 31;   // cell-update mapping
    unsigned* barp = g_bar + d * SS;

    for (int it = 0; it < SS; it++) {
        int t = d ? (SS - 1 - it) : it;

        // prefetch this step's xg into registers (DRAM latency hidden behind copy+GEMV)
        float xgv[4];
        const float* xgb = g_xg + ((size_t)(d * SS + t) * T4H) * BB;
#pragma unroll
        for (int gg = 0; gg < 4; gg++)
            xgv[gg] = xgb[(size_t)(gg * HH + m * 4 + u) * BB + b];

        if (it > 0) {
            // bulk stage h[t_prev] into smem (16 LDG.128/thread, high MLP)
            int tp = d ? t + 1 : t - 1;
            const float4* src = (const float4*)(g_h + (size_t)(d * SS + tp) * HH * BB);
            float4* dst = (float4*)h_s;
#pragma unroll
            for (int i = 0; i < 16; i++) dst[tid + i * 128] = src[tid + i * 128];
        }
        __syncthreads();

        if (it > 0) {
            ull a[4][2];
#pragma unroll
            for (int i = 0; i < 4; i++) { a[i][0] = 0ULL; a[i][1] = 0ULL; }
            int k0 = w * 64;
#pragma unroll 8
            for (int k = k0; k < k0 + 64; k++) {
                ulonglong2 w01 = Wd2[k * 8 + ggl * 2];
                ulonglong2 w23 = Wd2[k * 8 + ggl * 2 + 1];
                ulonglong2 hh  = H2[k * 8 + bg];
                a[0][0] = fma2(w01.x, hh.x, a[0][0]); a[0][1] = fma2(w01.x, hh.y, a[0][1]);
                a[1][0] = fma2(w01.y, hh.x, a[1][0]); a[1][1] = fma2(w01.y, hh.y, a[1][1]);
                a[2][0] = fma2(w23.x, hh.x, a[2][0]); a[2][1] = fma2(w23.x, hh.y, a[2][1]);
                a[3][0] = fma2(w23.y, hh.x, a[3][0]); a[3][1] = fma2(w23.y, hh.y, a[3][1]);
            }
#pragma unroll
            for (int i = 0; i < 4; i++) {
                ull* pr = part + (size_t)(w * 16 + ggl * 4 + i) * 17 + bg * 2;
                pr[0] = a[i][0]; pr[1] = a[i][1];
            }
        }
        __syncthreads();

        // cell update: thread -> (u, b)
        {
            const float* pf = (const float*)part;
            float g[4];
#pragma unroll
            for (int gg = 0; gg < 4; gg++) {
                float s = xgv[gg];
                if (it > 0) {
                    int r = gg * 4 + u;
#pragma unroll
                    for (int wi = 0; wi < 4; wi++)
                        s += pf[(((size_t)wi * 16 + r) * 17 + (b >> 1)) * 2 + (b & 1)];
                }
                g[gg] = s;
            }
            float iv = fsigmoid(g[0]);
            float fv = fsigmoid(g[1]);
            float gv = ftanh_fast(g[2]);
            float ov = fsigmoid(g[3]);
            float c = fv * c_s[tid] + iv * gv;
            c_s[tid] = c;
            g_h[((size_t)(d * SS + t) * HH + m * 4 + u) * BB + b] = ov * ftanh_fast(c);
        }
        __syncthreads();  // all block h-writes ordered before tid0's release

        if (tid == 0) {
            unsigned* bp = barp + it;
            asm volatile("red.release.gpu.global.add.u32 [%0], %1;" :: "l"(bp), "r"(1u) : "memory");
            unsigned v;
            do {
                asm volatile("ld.acquire.gpu.global.u32 %0, [%1];" : "=r"(v) : "l"(bp) : "memory");
            } while (v < 64u);
        }
        __syncthreads();  // broadcast acquire to whole block
    }
}

// ---------------- logits: [b][t][tag] = hcat . W_tag[tag] + b_tag ----------------
__global__ __launch_bounds__(256) void logits_kernel(const float* __restrict__ Wtag,
                                                     const float* __restrict__ btag) {
    extern __shared__ float hb[];  // [512 k][32 b]
    int t = blockIdx.x;
    int tid = threadIdx.x;
    for (int dd = 0; dd < 2; dd++) {
        const float4* src = (const float4*)(g_h + (size_t)(dd * SS + t) * HH * BB);
        float4* dst = (float4*)(hb + (size_t)dd * HH * BB);
        for (int i = tid; i < 2048; i += 256) dst[i] = src[i];
    }
    __syncthreads();
    for (int o = tid; o < BB * NT; o += 256) {
        int tag = o >> 5;
        int b = o & 31;
        float acc = btag[tag];
        const float* wr = Wtag + (size_t)tag * (2 * HH);
#pragma unroll 8
        for (int k = 0; k < 2 * HH; k++) acc += hb[k * BB + b] * wr[k];
        g_logits[((size_t)b * SS + t) * NT + tag] = acc;
    }
}

// ---------------- merged CRF forward + Viterbi (grid 32 x 2) ----------------
__global__ void crf_vit_kernel(const int* __restrict__ mask, const int* __restrict__ labels,
                               const float* __restrict__ trans, float* __restrict__ out) {
    __shared__ float tr[NT * NT];
    __shared__ float st[NT];
    int b = blockIdx.x, j = threadIdx.x;
    for (int i = j; i < NT * NT; i += 32) tr[i] = trans[i];
    __syncthreads();

    if (blockIdx.y == 0) {
        // ---- CRF NLL ----
        if (j < NT) st[j] = g_logits[((size_t)b * SS) * NT + j] + tr[TSTART * NT + j];
        __syncthreads();
        for (int t = 1; t < SS; t++) {
            int mt = mask[b * SS + t];
            float nv = 0.0f;
            if (j < NT) {
                float mx = -1e30f;
#pragma unroll
                for (int i = 0; i < NT; i++) mx = fmaxf(mx, st[i] + tr[i * NT + j]);
                float sum = 0.0f;
#pragma unroll
                for (int i = 0; i < NT; i++) sum += __expf(st[i] + tr[i * NT + j] - mx);
                nv = mx + __logf(sum) + g_logits[((size_t)b * SS + t) * NT + j];
            }
            __syncthreads();
            if (j < NT && mt > 0) st[j] = nv;
            __syncthreads();
        }
        if (j == 0) {
            float mx = -1e30f;
            for (int i = 0; i < NT; i++) mx = fmaxf(mx, st[i] + tr[i * NT + TSTOP]);
            float sum = 0.0f;
            for (int i = 0; i < NT; i++) sum += __expf(st[i] + tr[i * NT + TSTOP] - mx);
            float logZ = mx + __logf(sum);
            float gold = 0.0f;
            int prev = TSTART, len = 0;
            for (int t = 0; t < SS; t++) {
                int lab = labels[b * SS + t];
                if (mask[b * SS + t] > 0) {
                    gold += tr[prev * NT + lab] + g_logits[((size_t)b * SS + t) * NT + lab];
                    len++;
                }
                prev = lab;
            }
            int last = labels[b * SS + len - 1];
            gold += tr[last * NT + TSTOP];
            g_nll[b] = logZ - gold;
        }
    } else {
        // ---- Viterbi ----
        if (j < NT) st[j] = g_logits[((size_t)b * SS) * NT + j] + tr[TSTART * NT + j];
        __syncthreads();
        for (int t = 1; t < SS; t++) {
            int mt = mask[b * SS + t];
            float nv = 0.0f;
            int arg = j;
            if (j < NT) {
                float best = -1e30f;
                int bi = 0;
#pragma unroll
                for (int i = 0; i < NT; i++) {
                    float v = st[i] + tr[i * NT + j];
                    if (v > best) { best = v; bi = i; }  // strict '>' => first max (jnp.argmax)
                }
                nv = best + g_logits[((size_t)b * SS + t) * NT + j];
                if (mt > 0) arg = bi;
            }
            __syncthreads();
            if (j < NT) {
                if (mt > 0) st[j] = nv;
                g_ptr[((size_t)b * SS + t) * NT + j] = arg;
            }
            __syncthreads();
        }
        if (j == 0) {
            float best = -1e30f;
            int bl = 0;
            for (int i = 0; i < NT; i++) {
                float v = st[i] + tr[i * NT + TSTOP];
                if (v > best) { best = v; bl = i; }
            }
            int tag = bl;
            for (int t = SS - 1; t >= 1; t--) {
                out[1 + b * SS + t] = (float)(mask[b * SS + t] > 0 ? tag : 0);
                tag = g_ptr[((size_t)b * SS + t) * NT + tag];
            }
            out[1 + b * SS + 0] = (float)(mask[b * SS + 0] > 0 ? tag : 0);
        }
    }
}

__global__ void finalize_kernel(float* out) {
    if (threadIdx.x == 0) {
        float s = 0.0f;
        for (int i = 0; i < BB; i++) s += g_nll[i];
        out[0] = s / (float)BB;
    }
}

extern "C" void kernel_launch(void* const* d_in, const int* in_sizes, int n_in,
                              void* d_out, int out_size) {
    // metadata order: word, mask, labels, labels_token, [data_type], emb, WihF, WhhF,
    // bihF, bhhF, WihB, WhhB, bihB, bhhB, Wtag, btag, trans
    int o = (in_sizes[4] == 1) ? 0 : -1;  // data_type scalar present or dropped
    const int*   word   = (const int*)d_in[0];
    const int*   mask   = (const int*)d_in[1];
    const int*   labels = (const int*)d_in[2];
    const float* emb    = (const float*)d_in[5 + o];
    const float* WihF   = (const float*)d_in[6 + o];
    const float* WhhF   = (const float*)d_in[7 + o];
    const float* bihF   = (const float*)d_in[8 + o];
    const float* bhhF   = (const float*)d_in[9 + o];
    const float* WihB   = (const float*)d_in[10 + o];
    const float* WhhB   = (const float*)d_in[11 + o];
    const float* bihB   = (const float*)d_in[12 + o];
    const float* bhhB   = (const float*)d_in[13 + o];
    const float* Wtag   = (const float*)d_in[14 + o];
    const float* btag   = (const float*)d_in[15 + o];
    const float* trans  = (const float*)d_in[16 + o];
    float* out = (float*)d_out;

    const int lstm_smem = (4096 + 4096 + 1088) * 8 + 128 * 4;  // 74752 B
    cudaFuncSetAttribute(lstm_kernel, cudaFuncAttributeMaxDynamicSharedMemorySize, lstm_smem);
    cudaFuncSetAttribute(logits_kernel, cudaFuncAttributeMaxDynamicSharedMemorySize, 65536);

    int nz = out_size > 2 * SS ? out_size : 2 * SS;
    zero_out_kernel<<<(nz + 255) / 256, 256>>>(out, out_size);
    embed_kernel<<<(BB * SS * (EP / 4) + 255) / 256, 256>>>(word, mask, emb);
    {
        dim3 grid(BB * SS / 64, T4H / 64, 2);
        gemm_xg_kernel<<<grid, 256>>>(WihF, WihB, bihF, bhhF, bihB, bhhB);
    }
    lstm_kernel<<<128, 128, lstm_smem>>>(WhhF, WhhB);
    logits_kernel<<<SS, 256, 65536>>>(Wtag, btag);
    crf_vit_kernel<<<dim3(BB, 2), 32>>>(mask, labels, trans, out);
    finalize_kernel<<<1, 32>>>(out);
}

// round 5
// speedup vs baseline: 1.2040x; 1.0786x over previous
#include <cuda_runtime.h>
#include <math.h>

#define BB 32
#define SS 256
#define EE 300
#define EP 304
#define HH 256
#define T4H 1024
#define NT 19
#define TSTART 17
#define TSTOP 18

typedef unsigned long long ull;

__device__ __forceinline__ ull fma2(ull a, ull b, ull c) {
    ull d;
    asm("fma.rn.f32x2 %0, %1, %2, %3;" : "=l"(d) : "l"(a), "l"(b), "l"(c));
    return d;
}
__device__ __forceinline__ ull pack2(float lo, float hi) {
    ull r;
    asm("mov.b64 %0, {%1, %2};" : "=l"(r) : "f"(lo), "f"(hi));
    return r;
}
__device__ __forceinline__ float fsigmoid(float x) {
    return 1.0f / (1.0f + __expf(-x));
}
__device__ __forceinline__ float ftanh_fast(float x) {
    return 1.0f - 2.0f / (__expf(2.0f * x) + 1.0f);
}

// ---------------- device scratch (no cudaMalloc allowed) ----------------
__device__ float    g_X[(size_t)BB * SS * EP];            // [n][e], n = t*32 + b
__device__ float    g_xg[(size_t)2 * SS * T4H * BB];      // [d][t][row][b]
__device__ float    g_h[(size_t)2 * SS * HH * BB];        // [d][t][k][b]
__device__ float    g_logits[(size_t)BB * SS * NT];       // [b][t][tag]
__device__ int      g_ptr[(size_t)BB * SS * NT];          // viterbi backpointers
__device__ float    g_nll[BB];
__device__ unsigned g_bar[2 * SS * 4];                    // [dir][step][group] arrival counters

// ---------------- zero output + barrier counters ----------------
__global__ void zero_out_kernel(float* out, int n) {
    int i = blockIdx.x * blockDim.x + threadIdx.x;
    if (i < n) out[i] = 0.0f;
    if (i < 2 * SS * 4) g_bar[i] = 0u;
}

// ---------------- embedding gather + mask -> padded X [8192][304] ----------------
__global__ void embed_kernel(const int* __restrict__ word, const int* __restrict__ mask,
                             const float* __restrict__ emb) {
    int idx = blockIdx.x * blockDim.x + threadIdx.x;
    int total = BB * SS * (EP / 4);
    if (idx >= total) return;
    int n = idx / (EP / 4), q = idx - n * (EP / 4);
    int t = n >> 5, b = n & 31;
    int w = word[b * SS + t];
    float m = (float)mask[b * SS + t];
    int e = q * 4;
    float4 v;
    if (e < EE) {
        float4 ev = *(const float4*)(emb + (size_t)w * EE + e);
        v.x = ev.x * m; v.y = ev.y * m; v.z = ev.z * m; v.w = ev.w * m;
    } else {
        v.x = v.y = v.z = v.w = 0.0f;
    }
    ((float4*)g_X)[(size_t)n * (EP / 4) + q] = v;
}

// ---------------- input-transform GEMM (f32x2): xg = X @ Wih_d.T + bih + bhh ----------------
__global__ __launch_bounds__(256) void gemm_xg_kernel(
    const float* __restrict__ WihF, const float* __restrict__ WihB,
    const float* __restrict__ bihF, const float* __restrict__ bhhF,
    const float* __restrict__ bihB, const float* __restrict__ bhhB) {
    __shared__ ull   As[16][64];   // duplicated {w,w} pairs: [k][row]
    __shared__ float Xs[16][68];   // [k][col], pitch 68 keeps 16B alignment
    int d = blockIdx.z;
    const float* Wih = d ? WihB : WihF;
    const float* bih = d ? bihB : bihF;
    const float* bhh = d ? bhhB : bhhF;
    int m0 = blockIdx.y * 64, n0 = blockIdx.x * 64;
    int tid = threadIdx.x;
    int lm = tid >> 2, kq = (tid & 3) * 4;
    int tx = tid & 15, ty = tid >> 4;
    ull acc[4][2];
#pragma unroll
    for (int i = 0; i < 4; i++) { acc[i][0] = 0ULL; acc[i][1] = 0ULL; }

    for (int e0 = 0; e0 < EP; e0 += 16) {
        float4 a;
        if (e0 + kq < EE) {
            a = *(const float4*)(Wih + (size_t)(m0 + lm) * EE + e0 + kq);
        } else {
            a.x = a.y = a.z = a.w = 0.0f;
        }
        As[kq + 0][lm] = pack2(a.x, a.x);
        As[kq + 1][lm] = pack2(a.y, a.y);
        As[kq + 2][lm] = pack2(a.z, a.z);
        As[kq + 3][lm] = pack2(a.w, a.w);
        float4 xv = *(const float4*)(g_X + (size_t)(n0 + lm) * EP + e0 + kq);
        Xs[kq + 0][lm] = xv.x; Xs[kq + 1][lm] = xv.y; Xs[kq + 2][lm] = xv.z; Xs[kq + 3][lm] = xv.w;
        __syncthreads();
#pragma unroll
        for (int k = 0; k < 16; k++) {
            ulonglong2 w01 = *(const ulonglong2*)&As[k][ty * 4];
            ulonglong2 w23 = *(const ulonglong2*)&As[k][ty * 4 + 2];
            ulonglong2 xx  = *(const ulonglong2*)&Xs[k][tx * 4];
            acc[0][0] = fma2(w01.x, xx.x, acc[0][0]); acc[0][1] = fma2(w01.x, xx.y, acc[0][1]);
            acc[1][0] = fma2(w01.y, xx.x, acc[1][0]); acc[1][1] = fma2(w01.y, xx.y, acc[1][1]);
            acc[2][0] = fma2(w23.x, xx.x, acc[2][0]); acc[2][1] = fma2(w23.x, xx.y, acc[2][1]);
            acc[3][0] = fma2(w23.y, xx.x, acc[3][0]); acc[3][1] = fma2(w23.y, xx.y, acc[3][1]);
        }
        __syncthreads();
    }
#pragma unroll
    for (int i = 0; i < 4; i++) {
        int row = m0 + ty * 4 + i;
        float bias = bih[row] + bhh[row];
        float2 f0 = *(float2*)&acc[i][0];
        float2 f1 = *(float2*)&acc[i][1];
        float vals[4] = {f0.x, f0.y, f1.x, f1.y};
#pragma unroll
        for (int j = 0; j < 4; j++) {
            int n = n0 + tx * 4 + j;
            int tt = n >> 5, bb2 = n & 31;
            g_xg[(((size_t)d * SS + tt) * T4H + row) * BB + bb2] = vals[j] + bias;
        }
    }
}

// ---------------- persistent BiLSTM recurrence: producer-group dataflow sync ----------------
// 128 blocks: bid>>6 = dir, bid&63 = slice m (4 hidden units -> 16 gate rows).
// Warp w consumes h[k in 64w..64w+63] <- produced by blocks m in [16w,16w+16):
// per-(dir,step,group) counters; producers arrive and never wait.
__global__ __launch_bounds__(128, 1) void lstm_kernel(
    const float* __restrict__ WhhF, const float* __restrict__ WhhB) {
    extern __shared__ ull sm8[];
    ull*   W_dup = sm8;                     // [256 k][16 r] {w,w} pairs (4096 ull)
    float* h_s   = (float*)(sm8 + 4096);    // [256 k][32 b]            (4096 ull)
    ull*   part  = sm8 + 8192;              // [4 w][16 r][17 pairs]    (1088 ull)

    int tid = threadIdx.x, bid = blockIdx.x;
    int d = bid >> 6, m = bid & 63;
    const float* Whh = d ? WhhB : WhhF;

    for (int i = tid; i < 4096; i += 128) {
        int r = i & 15, k = i >> 4;
        int gg = r >> 2, uu = r & 3;
        float w = Whh[(size_t)(gg * HH + m * 4 + uu) * HH + k];
        W_dup[k * 16 + r] = pack2(w, w);
    }
    __syncthreads();

    int lane = tid & 31, w = tid >> 5;
    int ggl = lane & 3, bg = lane >> 2;
    const ulonglong2* Wd2 = (const ulonglong2*)W_dup;
    const ulonglong2* H2  = (const ulonglong2*)h_s;
    int u = tid >> 5, b = tid & 31;          // cell-update mapping
    float c_reg = 0.0f;                      // cell state lives in a register
    unsigned* barD = g_bar + d * SS * 4;
    int mygrp = m >> 4;                      // producer group of this block

    for (int it = 0; it < SS; it++) {
        int t = d ? (SS - 1 - it) : it;

        // prefetch this step's xg into registers (DRAM latency hidden behind poll+GEMV)
        float xgv[4];
        const float* xgb = g_xg + ((size_t)(d * SS + t) * T4H) * BB;
#pragma unroll
        for (int gg = 0; gg < 4; gg++)
            xgv[gg] = xgb[(size_t)(gg * HH + m * 4 + u) * BB + b];

        if (it > 0) {
            // wait only for this warp's 16 producers of step it-1
            unsigned* cp = barD + (it - 1) * 4 + w;
            unsigned v;
            do {
                asm volatile("ld.acquire.gpu.global.u32 %0, [%1];" : "=r"(v) : "l"(cp) : "memory");
            } while (v < 16u);

            // stage only this warp's k-range (warp-private region, no block sync)
            int tp = d ? t + 1 : t - 1;
            const float4* src4 = (const float4*)(g_h + (size_t)(d * SS + tp) * HH * BB);
            float4* dst4 = (float4*)h_s;
#pragma unroll
            for (int j = 0; j < 16; j++) {
                int idx = w * 512 + lane + j * 32;
                dst4[idx] = src4[idx];
            }
            __syncwarp();

            ull a[4][2];
#pragma unroll
            for (int i = 0; i < 4; i++) { a[i][0] = 0ULL; a[i][1] = 0ULL; }
            int k0 = w * 64;
#pragma unroll 8
            for (int k = k0; k < k0 + 64; k++) {
                ulonglong2 w01 = Wd2[k * 8 + ggl * 2];
                ulonglong2 w23 = Wd2[k * 8 + ggl * 2 + 1];
                ulonglong2 hh  = H2[k * 8 + bg];
                a[0][0] = fma2(w01.x, hh.x, a[0][0]); a[0][1] = fma2(w01.x, hh.y, a[0][1]);
                a[1][0] = fma2(w01.y, hh.x, a[1][0]); a[1][1] = fma2(w01.y, hh.y, a[1][1]);
                a[2][0] = fma2(w23.x, hh.x, a[2][0]); a[2][1] = fma2(w23.x, hh.y, a[2][1]);
                a[3][0] = fma2(w23.y, hh.x, a[3][0]); a[3][1] = fma2(w23.y, hh.y, a[3][1]);
            }
#pragma unroll
            for (int i = 0; i < 4; i++) {
                ull* pr = part + (size_t)(w * 16 + ggl * 4 + i) * 17 + bg * 2;
                pr[0] = a[i][0]; pr[1] = a[i][1];
            }
        }
        __syncthreads();   // parts from all 4 warps visible to cell phase

        // cell update: thread -> (u, b)
        {
            const float* pf = (const float*)part;
            float g[4];
#pragma unroll
            for (int gg = 0; gg < 4; gg++) {
                float s = xgv[gg];
                if (it > 0) {
                    int r = gg * 4 + u;
#pragma unroll
                    for (int wi = 0; wi < 4; wi++)
                        s += pf[(((size_t)wi * 16 + r) * 17 + (b >> 1)) * 2 + (b & 1)];
                }
                g[gg] = s;
            }
            float iv = fsigmoid(g[0]);
            float fv = fsigmoid(g[1]);
            float gv = ftanh_fast(g[2]);
            float ov = fsigmoid(g[3]);
            c_reg = fv * c_reg + iv * gv;
            g_h[((size_t)(d * SS + t) * HH + m * 4 + u) * BB + b] = ov * ftanh_fast(c_reg);
        }
        __syncthreads();   // h stores + part reads done before arrival / next GEMV overwrites part

        if (tid == 0) {
            unsigned* ap = barD + it * 4 + mygrp;
            asm volatile("red.release.gpu.global.add.u32 [%0], %1;" :: "l"(ap), "r"(1u) : "memory");
        }
        // no wait — proceed to next step; consumers gate themselves per warp
    }
}

// ---------------- logits: [b][t][tag] = hcat . W_tag[tag] + b_tag ----------------
__global__ __launch_bounds__(256) void logits_kernel(const float* __restrict__ Wtag,
                                                     const float* __restrict__ btag) {
    extern __shared__ float hb[];  // [512 k][32 b]
    int t = blockIdx.x;
    int tid = threadIdx.x;
    for (int dd = 0; dd < 2; dd++) {
        const float4* src = (const float4*)(g_h + (size_t)(dd * SS + t) * HH * BB);
        float4* dst = (float4*)(hb + (size_t)dd * HH * BB);
        for (int i = tid; i < 2048; i += 256) dst[i] = src[i];
    }
    __syncthreads();
    for (int o = tid; o < BB * NT; o += 256) {
        int tag = o >> 5;
        int b = o & 31;
        float acc = btag[tag];
        const float* wr = Wtag + (size_t)tag * (2 * HH);
#pragma unroll 8
        for (int k = 0; k < 2 * HH; k++) acc += hb[k * BB + b] * wr[k];
        g_logits[((size_t)b * SS + t) * NT + tag] = acc;
    }
}

// ---------------- merged CRF forward + Viterbi (grid 32 x 2) ----------------
__global__ void crf_vit_kernel(const int* __restrict__ mask, const int* __restrict__ labels,
                               const float* __restrict__ trans, float* __restrict__ out) {
    __shared__ float tr[NT * NT];
    __shared__ float st[NT];
    int b = blockIdx.x, j = threadIdx.x;
    for (int i = j; i < NT * NT; i += 32) tr[i] = trans[i];
    __syncthreads();

    if (blockIdx.y == 0) {
        // ---- CRF NLL ----
        if (j < NT) st[j] = g_logits[((size_t)b * SS) * NT + j] + tr[TSTART * NT + j];
        __syncthreads();
        for (int t = 1; t < SS; t++) {
            int mt = mask[b * SS + t];
            float nv = 0.0f;
            if (j < NT) {
                float mx = -1e30f;
#pragma unroll
                for (int i = 0; i < NT; i++) mx = fmaxf(mx, st[i] + tr[i * NT + j]);
                float sum = 0.0f;
#pragma unroll
                for (int i = 0; i < NT; i++) sum += __expf(st[i] + tr[i * NT + j] - mx);
                nv = mx + __logf(sum) + g_logits[((size_t)b * SS + t) * NT + j];
            }
            __syncthreads();
            if (j < NT && mt > 0) st[j] = nv;
            __syncthreads();
        }
        if (j == 0) {
            float mx = -1e30f;
            for (int i = 0; i < NT; i++) mx = fmaxf(mx, st[i] + tr[i * NT + TSTOP]);
            float sum = 0.0f;
            for (int i = 0; i < NT; i++) sum += __expf(st[i] + tr[i * NT + TSTOP] - mx);
            float logZ = mx + __logf(sum);
            float gold = 0.0f;
            int prev = TSTART, len = 0;
            for (int t = 0; t < SS; t++) {
                int lab = labels[b * SS + t];
                if (mask[b * SS + t] > 0) {
                    gold += tr[prev * NT + lab] + g_logits[((size_t)b * SS + t) * NT + lab];
                    len++;
                }
                prev = lab;
            }
            int last = labels[b * SS + len - 1];
            gold += tr[last * NT + TSTOP];
            g_nll[b] = logZ - gold;
        }
    } else {
        // ---- Viterbi ----
        if (j < NT) st[j] = g_logits[((size_t)b * SS) * NT + j] + tr[TSTART * NT + j];
        __syncthreads();
        for (int t = 1; t < SS; t++) {
            int mt = mask[b * SS + t];
            float nv = 0.0f;
            int arg = j;
            if (j < NT) {
                float best = -1e30f;
                int bi = 0;
#pragma unroll
                for (int i = 0; i < NT; i++) {
                    float v = st[i] + tr[i * NT + j];
                    if (v > best) { best = v; bi = i; }  // strict '>' => first max (jnp.argmax)
                }
                nv = best + g_logits[((size_t)b * SS + t) * NT + j];
                if (mt > 0) arg = bi;
            }
            __syncthreads();
            if (j < NT) {
                if (mt > 0) st[j] = nv;
                g_ptr[((size_t)b * SS + t) * NT + j] = arg;
            }
            __syncthreads();
        }
        if (j == 0) {
            float best = -1e30f;
            int bl = 0;
            for (int i = 0; i < NT; i++) {
                float v = st[i] + tr[i * NT + TSTOP];
                if (v > best) { best = v; bl = i; }
            }
            int tag = bl;
            for (int t = SS - 1; t >= 1; t--) {
                out[1 + b * SS + t] = (float)(mask[b * SS + t] > 0 ? tag : 0);
                tag = g_ptr[((size_t)b * SS + t) * NT + tag];
            }
            out[1 + b * SS + 0] = (float)(mask[b * SS + 0] > 0 ? tag : 0);
        }
    }
}

__global__ void finalize_kernel(float* out) {
    if (threadIdx.x == 0) {
        float s = 0.0f;
        for (int i = 0; i < BB; i++) s += g_nll[i];
        out[0] = s / (float)BB;
    }
}

extern "C" void kernel_launch(void* const* d_in, const int* in_sizes, int n_in,
                              void* d_out, int out_size) {
    // metadata order: word, mask, labels, labels_token, [data_type], emb, WihF, WhhF,
    // bihF, bhhF, WihB, WhhB, bihB, bhhB, Wtag, btag, trans
    int o = (in_sizes[4] == 1) ? 0 : -1;  // data_type scalar present or dropped
    const int*   word   = (const int*)d_in[0];
    const int*   mask   = (const int*)d_in[1];
    const int*   labels = (const int*)d_in[2];
    const float* emb    = (const float*)d_in[5 + o];
    const float* WihF   = (const float*)d_in[6 + o];
    const float* WhhF   = (const float*)d_in[7 + o];
    const float* bihF   = (const float*)d_in[8 + o];
    const float* bhhF   = (const float*)d_in[9 + o];
    const float* WihB   = (const float*)d_in[10 + o];
    const float* WhhB   = (const float*)d_in[11 + o];
    const float* bihB   = (const float*)d_in[12 + o];
    const float* bhhB   = (const float*)d_in[13 + o];
    const float* Wtag   = (const float*)d_in[14 + o];
    const float* btag   = (const float*)d_in[15 + o];
    const float* trans  = (const float*)d_in[16 + o];
    float* out = (float*)d_out;

    const int lstm_smem = (4096 + 4096 + 1088) * 8;  // 73472 B
    cudaFuncSetAttribute(lstm_kernel, cudaFuncAttributeMaxDynamicSharedMemorySize, lstm_smem);
    cudaFuncSetAttribute(logits_kernel, cudaFuncAttributeMaxDynamicSharedMemorySize, 65536);

    int nz = out_size > 2 * SS * 4 ? out_size : 2 * SS * 4;
    zero_out_kernel<<<(nz + 255) / 256, 256>>>(out, out_size);
    embed_kernel<<<(BB * SS * (EP / 4) + 255) / 256, 256>>>(word, mask, emb);
    {
        dim3 grid(BB * SS / 64, T4H / 64, 2);
        gemm_xg_kernel<<<grid, 256>>>(WihF, WihB, bihF, bhhF, bihB, bhhB);
    }
    lstm_kernel<<<128, 128, lstm_smem>>>(WhhF, WhhB);
    logits_kernel<<<SS, 256, 65536>>>(Wtag, btag);
    crf_vit_kernel<<<dim3(BB, 2), 32>>>(mask, labels, trans, out);
    finalize_kernel<<<1, 32>>>(out);
}